// round 1
// baseline (speedup 1.0000x reference)
#include <cuda_runtime.h>
#include <math.h>

#define B_MAX 4096

// Scratch (allocation-free): conv1 pooled output [B][16*14*14], dense angles [B][4]
__device__ float g_h1[B_MAX * 3136];
__device__ float g_ang[B_MAX * 4];

// ---------------------------------------------------------------------------
// Kernel 1: conv1 (1->16, 3x3, pad 1) + ReLU + 2x2 maxpool. One image per CTA.
// ---------------------------------------------------------------------------
__global__ __launch_bounds__(256) void k1_conv1(
    const float* __restrict__ x, const float* __restrict__ w,
    const float* __restrict__ b)
{
    __shared__ float sx[900];   // 30x30 zero-padded input
    __shared__ float sw[144];
    __shared__ float sb[16];

    const int img = blockIdx.x;
    const int t = threadIdx.x;
    const float* xi = x + img * 784;

    for (int i = t; i < 900; i += 256) {
        int r = i / 30, c = i % 30;
        float v = 0.f;
        if (r >= 1 && r <= 28 && c >= 1 && c <= 28) v = xi[(r - 1) * 28 + (c - 1)];
        sx[i] = v;
    }
    if (t < 144) sw[t] = w[t];
    if (t < 16)  sb[t] = b[t];
    __syncthreads();

    for (int idx = t; idx < 3136; idx += 256) {
        int ch = idx / 196, p = idx % 196;
        int pr = p / 14, pc = p % 14;
        float wr[9];
#pragma unroll
        for (int k = 0; k < 9; k++) wr[k] = sw[ch * 9 + k];
        const float bb = sb[ch];
        const int y0 = 2 * pr, x0 = 2 * pc;
        float pt[16];
#pragma unroll
        for (int rr = 0; rr < 4; rr++)
#pragma unroll
            for (int cc = 0; cc < 4; cc++)
                pt[rr * 4 + cc] = sx[(y0 + rr) * 30 + (x0 + cc)];
        float m = 0.f;  // relu folded: all pooled candidates >= 0 after relu
#pragma unroll
        for (int dr = 0; dr < 2; dr++)
#pragma unroll
            for (int dc = 0; dc < 2; dc++) {
                float s = bb;
#pragma unroll
                for (int kr = 0; kr < 3; kr++)
#pragma unroll
                    for (int kc = 0; kc < 3; kc++)
                        s = fmaf(pt[(dr + kr) * 4 + (dc + kc)], wr[kr * 3 + kc], s);
                m = fmaxf(m, s);
            }
        g_h1[img * 3136 + idx] = m;
    }
}

// ---------------------------------------------------------------------------
// Kernel 2: conv2 (16->32, 3x3, pad 1) + ReLU + 2x2 maxpool + dense (1568->4).
// One image per CTA, 224 threads = 32 out-channels x 7 pooled rows.
// smem padded to break bank conflicts: input rows stride 17, w2 ch stride 145.
// ---------------------------------------------------------------------------
#define K2_SIN   (16 * 272)            // 16 ch * 16 rows * 17 cols = 4352
#define K2_SW2   (32 * 145)            // 4640
#define K2_SDW   (4 * 1568)            // 6272
#define K2_FLOATS (K2_SIN + K2_SW2 + K2_SDW + 32 + 28)
#define K2_SMEM_BYTES (K2_FLOATS * 4)

__global__ __launch_bounds__(224) void k2_conv2_dense(
    const float* __restrict__ w2, const float* __restrict__ b2,
    const float* __restrict__ dw, const float* __restrict__ db)
{
    extern __shared__ float sm[];
    float* sin_ = sm;                      // [16][16*17] padded input
    float* sw2  = sm + K2_SIN;             // [32][145] (144 used)
    float* sdw  = sw2 + K2_SW2;            // [4][1568]
    float* sb2s = sdw + K2_SDW;            // [32]
    float* sred = sb2s + 32;               // [7][4]

    const int img = blockIdx.x;
    const int t = threadIdx.x;

    for (int i = t; i < K2_SIN; i += 224) sin_[i] = 0.f;
    __syncthreads();
    {
        const float* src = g_h1 + img * 3136;
        for (int i = t; i < 3136; i += 224) {
            int ch = i / 196, p = i % 196;
            int r = p / 14, c = p % 14;
            sin_[ch * 272 + (r + 1) * 17 + (c + 1)] = src[i];
        }
    }
    for (int i = t; i < 4608; i += 224) {
        int ch = i / 144, rest = i % 144;
        sw2[ch * 145 + rest] = w2[i];
    }
    for (int i = t; i < 6272; i += 224) sdw[i] = dw[i];
    if (t < 32) sb2s[t] = b2[t];
    __syncthreads();

    const int ch = t / 7;   // output channel 0..31
    const int pr = t % 7;   // pooled row 0..6

    float acc[28];          // 2 conv rows x 14 cols, bias pre-added
    {
        const float bb = sb2s[ch];
#pragma unroll
        for (int i = 0; i < 28; i++) acc[i] = bb;
    }

    const float* wbase = &sw2[ch * 145];
    for (int ic = 0; ic < 16; ic++) {
        float wr[9];
#pragma unroll
        for (int k = 0; k < 9; k++) wr[k] = wbase[ic * 9 + k];
        const float* rbase = &sin_[ic * 272 + (2 * pr) * 17];
#pragma unroll
        for (int j = 0; j < 4; j++) {
            float r[16];
#pragma unroll
            for (int cc = 0; cc < 16; cc++) r[cc] = rbase[j * 17 + cc];
#pragma unroll
            for (int o = 0; o < 2; o++) {
                const int kr = j - o;
                if (kr >= 0 && kr <= 2) {
#pragma unroll
                    for (int kc = 0; kc < 3; kc++) {
                        const float wv = wr[kr * 3 + kc];
#pragma unroll
                        for (int xx = 0; xx < 14; xx++)
                            acc[o * 14 + xx] = fmaf(r[xx + kc], wv, acc[o * 14 + xx]);
                    }
                }
            }
        }
    }

    // pool + relu + dense partials
    float a4[4] = {0.f, 0.f, 0.f, 0.f};
#pragma unroll
    for (int px = 0; px < 7; px++) {
        float p0 = fmaxf(acc[2 * px], acc[2 * px + 1]);
        float p1 = fmaxf(acc[14 + 2 * px], acc[14 + 2 * px + 1]);
        float pooled = fmaxf(fmaxf(p0, p1), 0.f);
        const int fi = ch * 49 + pr * 7 + px;
#pragma unroll
        for (int o = 0; o < 4; o++)
            a4[o] = fmaf(pooled, sdw[o * 1568 + fi], a4[o]);
    }

    // warp reduce (7 full warps)
#pragma unroll
    for (int o = 0; o < 4; o++)
#pragma unroll
        for (int off = 16; off > 0; off >>= 1)
            a4[o] += __shfl_down_sync(0xffffffffu, a4[o], off);
    const int lane = t & 31, wid = t >> 5;
    if (lane == 0) {
#pragma unroll
        for (int o = 0; o < 4; o++) sred[wid * 4 + o] = a4[o];
    }
    __syncthreads();
    if (t < 4) {
        float s = db[t];
#pragma unroll
        for (int w = 0; w < 7; w++) s += sred[w * 4 + t];
        g_ang[img * 4 + t] = s;
    }
}

// ---------------------------------------------------------------------------
// Kernel 3: 4-qubit statevector sim + post linear. One thread per image.
// ---------------------------------------------------------------------------
__device__ __forceinline__ float2 cmul(float2 a, float2 b) {
    return make_float2(fmaf(a.x, b.x, -a.y * b.y), fmaf(a.x, b.y, a.y * b.x));
}

__device__ __forceinline__ void ap1(float2* s, int bit,
                                    float2 m00, float2 m01, float2 m10, float2 m11)
{
#pragma unroll
    for (int i = 0; i < 16; i++) {
        if (!(i & bit)) {
            const int i1 = i | bit;
            float2 a0 = s[i], a1 = s[i1];
            float2 r0, r1;
            r0.x = m00.x * a0.x - m00.y * a0.y + m01.x * a1.x - m01.y * a1.y;
            r0.y = m00.x * a0.y + m00.y * a0.x + m01.x * a1.y + m01.y * a1.x;
            r1.x = m10.x * a0.x - m10.y * a0.y + m11.x * a1.x - m11.y * a1.y;
            r1.y = m10.x * a0.y + m10.y * a0.x + m11.x * a1.y + m11.y * a1.x;
            s[i] = r0; s[i1] = r1;
        }
    }
}

__global__ __launch_bounds__(256) void k3_quantum_post(
    const float* __restrict__ qp, const float* __restrict__ pw,
    const float* __restrict__ pb, float* __restrict__ out, int B)
{
    const int img = blockIdx.x * blockDim.x + threadIdx.x;
    if (img >= B) return;

    float2 s[16];
#pragma unroll
    for (int i = 0; i < 16; i++) s[i] = make_float2(0.f, 0.f);
    s[0] = make_float2(1.f, 0.f);

    // initial per-wire RY(pi*angle)
#pragma unroll
    for (int w = 0; w < 4; w++) {
        const float th = g_ang[img * 4 + w] * 3.14159265358979323846f * 0.5f;
        float sn, cs;
        sincosf(th, &sn, &cs);
        ap1(s, 8 >> w, make_float2(cs, 0.f), make_float2(-sn, 0.f),
            make_float2(sn, 0.f), make_float2(cs, 0.f));
    }

    const int pc_[6] = {0, 0, 0, 1, 1, 2};
    const int pt_[6] = {1, 2, 3, 2, 3, 3};

#pragma unroll
    for (int l = 0; l < 2; l++) {
        const int st = l * 18;
        // single-qubit rotations: M = RZ(g) RY(b) RX(a)
#pragma unroll
        for (int q = 0; q < 4; q++) {
            float a = qp[st + q * 3 + 0];
            float b = qp[st + q * 3 + 1];
            float g = qp[st + q * 3 + 2];
            float sa, ca, sb, cb, sg, cg;
            sincosf(a * 0.5f, &sa, &ca);
            sincosf(b * 0.5f, &sb, &cb);
            sincosf(g * 0.5f, &sg, &cg);
            // RY@RX
            float2 m00 = make_float2(cb * ca,  sb * sa);
            float2 m01 = make_float2(-sb * ca, -cb * sa);
            float2 m10 = make_float2(sb * ca,  -cb * sa);
            float2 m11 = make_float2(cb * ca,  -sb * sa);
            const float2 em = make_float2(cg, -sg);  // e^{-i g/2}
            const float2 ep = make_float2(cg,  sg);  // e^{+i g/2}
            m00 = cmul(em, m00); m01 = cmul(em, m01);
            m10 = cmul(ep, m10); m11 = cmul(ep, m11);
            ap1(s, 8 >> q, m00, m01, m10, m11);
        }
        // entanglers: M4 = kron(I, RZ(phi)) @ CNOT
#pragma unroll
        for (int k = 0; k < 6; k++) {
            const float phi = qp[st + 12 + k] * 0.5f;
            float sp, cp;
            sincosf(phi, &sp, &cp);
            const float2 em = make_float2(cp, -sp);
            const float2 ep = make_float2(cp,  sp);
            const int bc = 8 >> pc_[k];
            const int bt = 8 >> pt_[k];
#pragma unroll
            for (int base = 0; base < 16; base++) {
                if (!(base & (bc | bt))) {
                    const int i01 = base | bt, i10 = base | bc, i11 = base | bc | bt;
                    float2 t00 = s[base], t01 = s[i01], t10 = s[i10], t11 = s[i11];
                    s[base] = cmul(em, t00);
                    s[i01]  = cmul(ep, t01);
                    s[i10]  = cmul(em, t11);
                    s[i11]  = cmul(ep, t10);
                }
            }
        }
    }

    // Z expectations
    float z[4];
#pragma unroll
    for (int w = 0; w < 4; w++) {
        const int bit = 8 >> w;
        float zv = 0.f;
#pragma unroll
        for (int i = 0; i < 16; i++) {
            const float p = s[i].x * s[i].x + s[i].y * s[i].y;
            zv += (i & bit) ? -p : p;
        }
        z[w] = zv;
    }

    // post linear (4 -> 10)
#pragma unroll
    for (int k = 0; k < 10; k++) {
        float o = pb[k];
#pragma unroll
        for (int j = 0; j < 4; j++) o = fmaf(z[j], pw[k * 4 + j], o);
        out[img * 10 + k] = o;
    }
}

// ---------------------------------------------------------------------------
extern "C" void kernel_launch(void* const* d_in, const int* in_sizes, int n_in,
                              void* d_out, int out_size)
{
    const float* x    = (const float*)d_in[0];
    const float* c1w  = (const float*)d_in[1];
    const float* c1b  = (const float*)d_in[2];
    const float* c2w  = (const float*)d_in[3];
    const float* c2b  = (const float*)d_in[4];
    const float* dw   = (const float*)d_in[5];
    const float* db   = (const float*)d_in[6];
    const float* qp   = (const float*)d_in[7];
    const float* pw   = (const float*)d_in[8];
    const float* pb   = (const float*)d_in[9];
    float* out = (float*)d_out;

    int B = in_sizes[0] / 784;
    if (B > B_MAX) B = B_MAX;

    cudaFuncSetAttribute(k2_conv2_dense,
                         cudaFuncAttributeMaxDynamicSharedMemorySize,
                         K2_SMEM_BYTES);

    k1_conv1<<<B, 256>>>(x, c1w, c1b);
    k2_conv2_dense<<<B, 224, K2_SMEM_BYTES>>>(c2w, c2b, dw, db);
    k3_quantum_post<<<(B + 255) / 256, 256>>>(qp, pw, pb, out, B);
}